// round 15
// baseline (speedup 1.0000x reference)
#include <cuda_runtime.h>
#include <cuda_bf16.h>
#include <cuda_fp16.h>
#include <math_constants.h>
#include <cstdint>

#define N_TOKENS 100000
#define N_ARGS   20000
#define N_EDGES  320000
#define IN_DIM   768
#define HEADS    8
#define OUT_DIM  64
#define Z_DIM    (HEADS*OUT_DIM)   // 512

// ---------------- scratch (static __device__, no allocation) ----------------
__device__ float g_v[HEADS*IN_DIM];
__device__ float g_enode[N_TOKENS*HEADS];
__device__ int   g_counts[N_ARGS];          // zero-init at load; k3 re-zeroes
__device__ int   g_offsets[N_ARGS+1];
__device__ int   g_cursor[N_ARGS];
__device__ int   g_perm_src[N_EDGES];
__device__ __half g_hbar[(size_t)HEADS*N_ARGS*IN_DIM];   // fp16 plane, 245.8 MB
__device__ __half g_Whf[Z_DIM*IN_DIM];                   // W fp16 hi
__device__ __half g_Wlf[Z_DIM*IN_DIM];                   // W fp16 lo (residual)

// ---------------- packed f32x2 helpers --------------------------------------
__device__ __forceinline__ unsigned long long fma_f32x2(unsigned long long a,
                                                        unsigned long long b,
                                                        unsigned long long c)
{
    unsigned long long d;
    asm("fma.rn.f32x2 %0, %1, %2, %3;" : "=l"(d) : "l"(a), "l"(b), "l"(c));
    return d;
}

// ---------------- K0: v[h][k] = sum_d a_attn[d] * W_fc[h*64+d][k] ----------
__global__ void k0_attn_proj(const float* __restrict__ W, const float* __restrict__ a)
{
    int t = blockIdx.x * blockDim.x + threadIdx.x;
    if (t >= HEADS*IN_DIM) return;
    int hh = t / IN_DIM;
    int k  = t % IN_DIM;
    float acc = 0.f;
    #pragma unroll 8
    for (int d = 0; d < OUT_DIM; d++)
        acc += a[d] * W[(size_t)(hh*OUT_DIM + d)*IN_DIM + k];
    g_v[t] = acc;
}

// ---------------- K0b: split W into fp16 hi/lo -----------------------------
__global__ void k0b_wsplit(const float* __restrict__ W)
{
    int t = blockIdx.x * blockDim.x + threadIdx.x;
    if (t >= Z_DIM*IN_DIM) return;
    float w = W[t];
    __half hi = __float2half_rn(w);
    float lof = w - __half2float(hi);
    g_Whf[t] = hi;
    g_Wlf[t] = __float2half_rn(lof);
}

// ---------------- K1: e_node = leaky_relu(h @ v), 2 tokens/warp ------------
__global__ __launch_bounds__(256) void k1_scores(const float* __restrict__ h)
{
    __shared__ float vs[HEADS*IN_DIM];   // 24 KB
    int tid = threadIdx.x;
    for (int i = tid; i < HEADS*IN_DIM; i += 256) vs[i] = g_v[i];
    __syncthreads();

    int warp = blockIdx.x * 8 + (tid >> 5);
    int lane = tid & 31;
    int n0 = warp * 2;                    // 50000 warps cover 100000 tokens
    if (n0 >= N_TOKENS) return;

    const float4* h4  = (const float4*)h;
    const float4* vs4 = (const float4*)vs;

    float acc[16];
    #pragma unroll
    for (int j = 0; j < 16; j++) acc[j] = 0.f;

    #pragma unroll
    for (int t = 0; t < 6; t++) {
        float4 x0 = h4[(size_t)(n0    )*192 + lane + 32*t];
        float4 x1 = h4[(size_t)(n0 + 1)*192 + lane + 32*t];
        #pragma unroll
        for (int hh = 0; hh < 8; hh++) {
            float4 vv = vs4[hh*192 + lane + 32*t];
            acc[hh]   += x0.x*vv.x + x0.y*vv.y + x0.z*vv.z + x0.w*vv.w;
            acc[8+hh] += x1.x*vv.x + x1.y*vv.y + x1.z*vv.z + x1.w*vv.w;
        }
    }

    float res = 0.f;
    #pragma unroll
    for (int j = 0; j < 16; j++) {
        float v = acc[j];
        v += __shfl_xor_sync(0xffffffffu, v, 16);
        v += __shfl_xor_sync(0xffffffffu, v, 8);
        v += __shfl_xor_sync(0xffffffffu, v, 4);
        v += __shfl_xor_sync(0xffffffffu, v, 2);
        v += __shfl_xor_sync(0xffffffffu, v, 1);
        if (lane == j) res = v;
    }
    if (lane < 16) {
        int tok = n0 + (lane >> 3);
        int hh  = lane & 7;
        float e = (res >= 0.f) ? res : 0.01f * res;
        g_enode[(size_t)tok*HEADS + hh] = e;
    }
}

// ---------------- K2b: histogram -------------------------------------------
__global__ void k2b_hist(const int* __restrict__ dst)
{
    int e = blockIdx.x * blockDim.x + threadIdx.x;
    if (e < N_EDGES) atomicAdd(&g_counts[dst[e]], 1);
}

// ---------------- K3: exclusive scan; re-zeroes counts ---------------------
__global__ __launch_bounds__(1024) void k3_scan(void)
{
    __shared__ int ssum[1024];
    const int PER = (N_ARGS + 1023) / 1024;
    int t = threadIdx.x;
    int base = t * PER;
    int s = 0;
    for (int i = 0; i < PER; i++) {
        int idx = base + i;
        if (idx < N_ARGS) s += g_counts[idx];
    }
    ssum[t] = s;
    __syncthreads();
    for (int off = 1; off < 1024; off <<= 1) {
        int v = (t >= off) ? ssum[t-off] : 0;
        __syncthreads();
        ssum[t] += v;
        __syncthreads();
    }
    int run = (t == 0) ? 0 : ssum[t-1];
    for (int i = 0; i < PER; i++) {
        int idx = base + i;
        if (idx < N_ARGS) {
            g_offsets[idx] = run;
            g_cursor[idx]  = run;
            run += g_counts[idx];
            g_counts[idx] = 0;
        }
    }
    if (t == 1023) g_offsets[N_ARGS] = ssum[1023];
}

// ---------------- K4: scatter ----------------------------------------------
__global__ void k4_scatter(const int* __restrict__ src, const int* __restrict__ dst)
{
    int e = blockIdx.x * blockDim.x + threadIdx.x;
    if (e < N_EDGES) {
        int d = dst[e];
        int pos = atomicAdd(&g_cursor[d], 1);
        g_perm_src[pos] = src[e];
    }
}

// ---------------- K5: per-dst softmax + weighted gather (packed f32x2) -----
// IDEMPOTENT: reads offsets/perm/enode/h; writes g_hbar only. Launched twice
// this round to measure its cost (dur delta vs 557us baseline).
__global__ __launch_bounds__(384) void k5_aggregate(const float* __restrict__ h)
{
    __shared__ float m_s[HEADS];
    __shared__ float rden_s[HEADS];
    __shared__ unsigned long long alpha2_s[64*HEADS];
    __shared__ int   src_s[64];

    int d   = blockIdx.x;
    int tid = threadIdx.x;
    int warp = tid >> 5;
    int lane = tid & 31;

    int beg = g_offsets[d];
    int end = g_offsets[d+1];
    int cnt = end - beg;

    unsigned long long acc2[8];
    #pragma unroll
    for (int hh = 0; hh < 8; hh++) acc2[hh] = 0ull;

    if (cnt > 0) {
        if (warp < 8) {
            float mv = -CUDART_INF_F;
            for (int i = lane; i < cnt; i += 32) {
                int s = g_perm_src[beg + i];
                mv = fmaxf(mv, g_enode[(size_t)s*HEADS + warp]);
            }
            #pragma unroll
            for (int off = 16; off > 0; off >>= 1)
                mv = fmaxf(mv, __shfl_xor_sync(0xffffffffu, mv, off));
            if (lane == 0) m_s[warp] = mv;
        }
        __syncthreads();

        if (warp < 8) {
            float mm = m_s[warp];
            float sv = 0.f;
            for (int i = lane; i < cnt; i += 32) {
                int s = g_perm_src[beg + i];
                sv += __expf(g_enode[(size_t)s*HEADS + warp] - mm);
            }
            #pragma unroll
            for (int off = 16; off > 0; off >>= 1)
                sv += __shfl_xor_sync(0xffffffffu, sv, off);
            if (lane == 0) rden_s[warp] = 1.0f / sv;
        }
        __syncthreads();

        for (int c0 = 0; c0 < cnt; c0 += 64) {
            int rem = min(64, cnt - c0);
            if (tid < rem) src_s[tid] = g_perm_src[beg + c0 + tid];
            __syncthreads();
            for (int t = tid; t < rem * 8; t += 384) {
                int i  = t >> 3;
                int hh = t & 7;
                int s = src_s[i];
                float al = __expf(g_enode[(size_t)s*HEADS + hh] - m_s[hh]) * rden_s[hh];
                unsigned int ab = __float_as_uint(al);
                alpha2_s[t] = ((unsigned long long)ab << 32) | (unsigned long long)ab;
            }
            __syncthreads();

            int i = 0;
            for (; i + 2 <= rem; i += 2) {
                const unsigned long long* hp0 =
                    (const unsigned long long*)(h + (size_t)src_s[i]*IN_DIM);
                const unsigned long long* hp1 =
                    (const unsigned long long*)(h + (size_t)src_s[i+1]*IN_DIM);
                unsigned long long x0 = hp0[tid];
                unsigned long long x1 = hp1[tid];
                const unsigned long long* ap0 = &alpha2_s[i*8];
                const unsigned long long* ap1 = ap0 + 8;
                #pragma unroll
                for (int hh = 0; hh < 8; hh++)
                    acc2[hh] = fma_f32x2(ap0[hh], x0, acc2[hh]);
                #pragma unroll
                for (int hh = 0; hh < 8; hh++)
                    acc2[hh] = fma_f32x2(ap1[hh], x1, acc2[hh]);
            }
            if (i < rem) {
                const unsigned long long* hp =
                    (const unsigned long long*)(h + (size_t)src_s[i]*IN_DIM);
                unsigned long long x = hp[tid];
                const unsigned long long* ap = &alpha2_s[i*8];
                #pragma unroll
                for (int hh = 0; hh < 8; hh++)
                    acc2[hh] = fma_f32x2(ap[hh], x, acc2[hh]);
            }
            __syncthreads();
        }
    }

    // epilogue: fp16 plane [head][d][k]
    #pragma unroll
    for (int hh = 0; hh < 8; hh++) {
        float vlo = __uint_as_float((unsigned int)acc2[hh]);
        float vhi = __uint_as_float((unsigned int)(acc2[hh] >> 32));
        __half2 hv = __floats2half2_rn(vlo, vhi);
        size_t base = ((size_t)hh*N_ARGS + d)*IN_DIM + 2*tid;
        *(__half2*)&g_hbar[base] = hv;
    }
}

// ---------------- K6: fp16 MMA GEMM, A fp16, B fp16 hi/lo, cp.async 3-stage -
#define GBM 128
#define GBN 64
#define GBK2 32
#define KPAD2 40
#define STAGES 3
#define A_ELE (GBM*KPAD2)             // 5120
#define B_ELE (GBN*KPAD2)             // 2560
#define STAGE_ELE (A_ELE + 2*B_ELE)   // 10240 halves = 20480 B
#define K6_SMEM (STAGES*STAGE_ELE*2)  // 61440 B

__device__ __forceinline__ void ldsm4(uint32_t* r, const void* p)
{
    uint32_t a = (uint32_t)__cvta_generic_to_shared(p);
    asm volatile("ldmatrix.sync.aligned.m8n8.x4.shared.b16 {%0,%1,%2,%3}, [%4];"
        : "=r"(r[0]), "=r"(r[1]), "=r"(r[2]), "=r"(r[3]) : "r"(a));
}
__device__ __forceinline__ void mma16816f(float* c, const uint32_t* a, const uint32_t* b)
{
    asm volatile("mma.sync.aligned.m16n8k16.row.col.f32.f16.f16.f32 "
        "{%0,%1,%2,%3},{%4,%5,%6,%7},{%8,%9},{%0,%1,%2,%3};"
        : "+f"(c[0]), "+f"(c[1]), "+f"(c[2]), "+f"(c[3])
        : "r"(a[0]), "r"(a[1]), "r"(a[2]), "r"(a[3]), "r"(b[0]), "r"(b[1]));
}
__device__ __forceinline__ void cp16(void* smem_dst, const void* gsrc, int src_size)
{
    uint32_t s = (uint32_t)__cvta_generic_to_shared(smem_dst);
    asm volatile("cp.async.cg.shared.global [%0], [%1], 16, %2;"
        :: "r"(s), "l"(gsrc), "r"(src_size));
}

__global__ __launch_bounds__(256) void k6_mma(float* __restrict__ out)
{
    extern __shared__ __half sm[];

    int tid = threadIdx.x;
    int d0  = blockIdx.x * GBM;
    int hh  = blockIdx.y;

    const __half* A  = g_hbar + (size_t)hh*N_ARGS*IN_DIM;
    const __half* Bh = g_Whf + (size_t)hh*OUT_DIM*IN_DIM;
    const __half* Bl = g_Wlf + (size_t)hh*OUT_DIM*IN_DIM;

    int ar0 = tid >> 2,        as0 = (tid & 3) * 8;
    int ar1 = (tid+256) >> 2;
    int br  = tid >> 2;

    int add0 = d0 + ar0, add1 = d0 + ar1;
    int av0 = (add0 < N_ARGS) ? 16 : 0;
    int av1 = (add1 < N_ARGS) ? 16 : 0;
    if (add0 >= N_ARGS) add0 = N_ARGS-1;
    if (add1 >= N_ARGS) add1 = N_ARGS-1;

    auto issue_stage = [&](int slot, int kbase) {
        __half* st  = sm + slot*STAGE_ELE;
        __half* sA  = st;
        __half* sBh = st + A_ELE;
        __half* sBl = st + A_ELE + B_ELE;
        cp16(sA + ar0*KPAD2 + as0, A + (size_t)add0*IN_DIM + kbase + as0, av0);
        cp16(sA + ar1*KPAD2 + as0, A + (size_t)add1*IN_DIM + kbase + as0, av1);
        cp16(sBh + br*KPAD2 + as0, Bh + (size_t)br*IN_DIM + kbase + as0, 16);
        cp16(sBl + br*KPAD2 + as0, Bl + (size_t)br*IN_DIM + kbase + as0, 16);
        asm volatile("cp.async.commit_group;");
    };

    int w    = tid >> 5;
    int lane = tid & 31;
    int wm   = (w & 3) * 32;
    int wn   = (w >> 2) * 32;

    int a_row = (lane & 15);
    int a_kof = (lane >> 4) * 8;
    int b_row = ((lane >> 4) << 3) + (lane & 7);
    int b_kof = (lane & 8);

    float acc[2][4][4];
    #pragma unroll
    for (int i = 0; i < 2; i++)
        #pragma unroll
        for (int j = 0; j < 4; j++)
            #pragma unroll
            for (int q = 0; q < 4; q++) acc[i][j][q] = 0.f;

    issue_stage(0, 0);
    issue_stage(1, GBK2);

    const int KT = IN_DIM / GBK2;   // 24
    for (int kt = 0; kt < KT; kt++) {
        asm volatile("cp.async.wait_group 1;");
        __syncthreads();
        if (kt + 2 < KT) issue_stage((kt+2) % STAGES, (kt+2)*GBK2);

        int cur = kt % STAGES;
        __half* st  = sm + cur*STAGE_ELE;
        __half* sA  = st;
        __half* sBh = st + A_ELE;
        __half* sBl = st + A_ELE + B_ELE;

        #pragma unroll
        for (int kh = 0; kh < 2; kh++) {
            uint32_t a[2][4], bh[2][4], bl[2][4];
            #pragma unroll
            for (int mb = 0; mb < 2; mb++)
                ldsm4(a[mb], sA + (wm + mb*16 + a_row)*KPAD2 + a_kof + kh*16);
            #pragma unroll
            for (int nb = 0; nb < 2; nb++) {
                ldsm4(bh[nb], sBh + (wn + nb*16 + b_row)*KPAD2 + b_kof + kh*16);
                ldsm4(bl[nb], sBl + (wn + nb*16 + b_row)*KPAD2 + b_kof + kh*16);
            }
            #pragma unroll
            for (int mb = 0; mb < 2; mb++) {
                #pragma unroll
                for (int nb = 0; nb < 4; nb++) {
                    const uint32_t* bhf = &bh[nb>>1][(nb&1)*2];
                    const uint32_t* blf = &bl[nb>>1][(nb&1)*2];
                    mma16816f(acc[mb][nb], a[mb], bhf);
                    mma16816f(acc[mb][nb], a[mb], blf);
                }
            }
        }
        __syncthreads();
    }

    int erow = lane >> 2;
    int ecol = (lane & 3) * 2;
    #pragma unroll
    for (int mb = 0; mb < 2; mb++) {
        #pragma unroll
        for (int nb = 0; nb < 4; nb++) {
            int col = hh*OUT_DIM + wn + nb*8 + ecol;
            int r0 = d0 + wm + mb*16 + erow;
            int r1 = r0 + 8;
            if (r0 < N_ARGS)
                *(float2*)(out + (size_t)r0*Z_DIM + col) =
                    make_float2(acc[mb][nb][0], acc[mb][nb][1]);
            if (r1 < N_ARGS)
                *(float2*)(out + (size_t)r1*Z_DIM + col) =
                    make_float2(acc[mb][nb][2], acc[mb][nb][3]);
        }
    }
}

// ---------------- launch ----------------------------------------------------
extern "C" void kernel_launch(void* const* d_in, const int* in_sizes, int n_in,
                              void* d_out, int out_size)
{
    const float* h     = (const float*)d_in[0];
    const float* W_fc  = (const float*)d_in[1];
    const float* a_att = (const float*)d_in[2];
    const int*   esrc  = (const int*)d_in[3];
    const int*   edst  = (const int*)d_in[4];
    float* out = (float*)d_out;

    cudaFuncSetAttribute(k6_mma, cudaFuncAttributeMaxDynamicSharedMemorySize, K6_SMEM);

    k0_attn_proj<<<(HEADS*IN_DIM + 255)/256, 256>>>(W_fc, a_att);
    k0b_wsplit<<<(Z_DIM*IN_DIM + 255)/256, 256>>>(W_fc);
    k2b_hist<<<(N_EDGES + 255)/256, 256>>>(edst);
    k1_scores<<<(N_TOKENS/2 + 7)/8, 256>>>(h);     // slot 4 -> ncu profiles this
    k3_scan<<<1, 1024>>>();
    k4_scatter<<<(N_EDGES + 255)/256, 256>>>(esrc, edst);
    k5_aggregate<<<N_ARGS, 384>>>(h);
    k5_aggregate<<<N_ARGS, 384>>>(h);  // MEASUREMENT: dup (idempotent); Δdur vs 557us = K5 cost
    dim3 g6((N_ARGS + GBM - 1)/GBM, HEADS);
    k6_mma<<<g6, 256, K6_SMEM>>>(out);
}

// round 16
// speedup vs baseline: 1.8340x; 1.8340x over previous
#include <cuda_runtime.h>
#include <cuda_bf16.h>
#include <cuda_fp16.h>
#include <math_constants.h>
#include <cstdint>

#define N_TOKENS 100000
#define N_ARGS   20000
#define N_EDGES  320000
#define IN_DIM   768
#define HEADS    8
#define OUT_DIM  64
#define Z_DIM    (HEADS*OUT_DIM)   // 512

// ---------------- scratch (static __device__, no allocation) ----------------
__device__ float g_v[HEADS*IN_DIM];
__device__ float g_enode[N_TOKENS*HEADS];
__device__ int   g_counts[N_ARGS];          // zero-init at load; k3 re-zeroes
__device__ int   g_offsets[N_ARGS+1];
__device__ int   g_cursor[N_ARGS];
__device__ int   g_perm_src[N_EDGES];
__device__ float g_alpha[(size_t)N_EDGES*HEADS];         // exp -> normalized alpha
__device__ __half g_hbar[(size_t)HEADS*N_ARGS*IN_DIM];   // fp16 plane, 245.8 MB
__device__ __half g_Whf[Z_DIM*IN_DIM];                   // W fp16 hi
__device__ __half g_Wlf[Z_DIM*IN_DIM];                   // W fp16 lo (residual)

// ---------------- packed f32x2 helpers --------------------------------------
__device__ __forceinline__ unsigned long long fma_f32x2(unsigned long long a,
                                                        unsigned long long b,
                                                        unsigned long long c)
{
    unsigned long long d;
    asm("fma.rn.f32x2 %0, %1, %2, %3;" : "=l"(d) : "l"(a), "l"(b), "l"(c));
    return d;
}

// ---------------- K0: v[h][k] = sum_d a_attn[d] * W_fc[h*64+d][k] ----------
__global__ void k0_attn_proj(const float* __restrict__ W, const float* __restrict__ a)
{
    int t = blockIdx.x * blockDim.x + threadIdx.x;
    if (t >= HEADS*IN_DIM) return;
    int hh = t / IN_DIM;
    int k  = t % IN_DIM;
    float acc = 0.f;
    #pragma unroll 8
    for (int d = 0; d < OUT_DIM; d++)
        acc += a[d] * W[(size_t)(hh*OUT_DIM + d)*IN_DIM + k];
    g_v[t] = acc;
}

// ---------------- K0b: split W into fp16 hi/lo -----------------------------
__global__ void k0b_wsplit(const float* __restrict__ W)
{
    int t = blockIdx.x * blockDim.x + threadIdx.x;
    if (t >= Z_DIM*IN_DIM) return;
    float w = W[t];
    __half hi = __float2half_rn(w);
    float lof = w - __half2float(hi);
    g_Whf[t] = hi;
    g_Wlf[t] = __float2half_rn(lof);
}

// ---------------- K1: e_node = leaky_relu(h @ v), 2 tokens/warp ------------
__global__ __launch_bounds__(256) void k1_scores(const float* __restrict__ h)
{
    __shared__ float vs[HEADS*IN_DIM];   // 24 KB
    int tid = threadIdx.x;
    for (int i = tid; i < HEADS*IN_DIM; i += 256) vs[i] = g_v[i];
    __syncthreads();

    int warp = blockIdx.x * 8 + (tid >> 5);
    int lane = tid & 31;
    int n0 = warp * 2;
    if (n0 >= N_TOKENS) return;

    const float4* h4  = (const float4*)h;
    const float4* vs4 = (const float4*)vs;

    float acc[16];
    #pragma unroll
    for (int j = 0; j < 16; j++) acc[j] = 0.f;

    #pragma unroll
    for (int t = 0; t < 6; t++) {
        float4 x0 = h4[(size_t)(n0    )*192 + lane + 32*t];
        float4 x1 = h4[(size_t)(n0 + 1)*192 + lane + 32*t];
        #pragma unroll
        for (int hh = 0; hh < 8; hh++) {
            float4 vv = vs4[hh*192 + lane + 32*t];
            acc[hh]   += x0.x*vv.x + x0.y*vv.y + x0.z*vv.z + x0.w*vv.w;
            acc[8+hh] += x1.x*vv.x + x1.y*vv.y + x1.z*vv.z + x1.w*vv.w;
        }
    }

    float res = 0.f;
    #pragma unroll
    for (int j = 0; j < 16; j++) {
        float v = acc[j];
        v += __shfl_xor_sync(0xffffffffu, v, 16);
        v += __shfl_xor_sync(0xffffffffu, v, 8);
        v += __shfl_xor_sync(0xffffffffu, v, 4);
        v += __shfl_xor_sync(0xffffffffu, v, 2);
        v += __shfl_xor_sync(0xffffffffu, v, 1);
        if (lane == j) res = v;
    }
    if (lane < 16) {
        int tok = n0 + (lane >> 3);
        int hh  = lane & 7;
        float e = (res >= 0.f) ? res : 0.01f * res;
        g_enode[(size_t)tok*HEADS + hh] = e;
    }
}

// ---------------- K2b: histogram -------------------------------------------
__global__ void k2b_hist(const int* __restrict__ dst)
{
    int e = blockIdx.x * blockDim.x + threadIdx.x;
    if (e < N_EDGES) atomicAdd(&g_counts[dst[e]], 1);
}

// ---------------- K3: exclusive scan; re-zeroes counts ---------------------
__global__ __launch_bounds__(1024) void k3_scan(void)
{
    __shared__ int ssum[1024];
    const int PER = (N_ARGS + 1023) / 1024;
    int t = threadIdx.x;
    int base = t * PER;
    int s = 0;
    for (int i = 0; i < PER; i++) {
        int idx = base + i;
        if (idx < N_ARGS) s += g_counts[idx];
    }
    ssum[t] = s;
    __syncthreads();
    for (int off = 1; off < 1024; off <<= 1) {
        int v = (t >= off) ? ssum[t-off] : 0;
        __syncthreads();
        ssum[t] += v;
        __syncthreads();
    }
    int run = (t == 0) ? 0 : ssum[t-1];
    for (int i = 0; i < PER; i++) {
        int idx = base + i;
        if (idx < N_ARGS) {
            g_offsets[idx] = run;
            g_cursor[idx]  = run;
            run += g_counts[idx];
            g_counts[idx] = 0;
        }
    }
    if (t == 1023) g_offsets[N_ARGS] = ssum[1023];
}

// ---------------- K4: scatter ----------------------------------------------
__global__ void k4_scatter(const int* __restrict__ src, const int* __restrict__ dst)
{
    int e = blockIdx.x * blockDim.x + threadIdx.x;
    if (e < N_EDGES) {
        int d = dst[e];
        int pos = atomicAdd(&g_cursor[d], 1);
        g_perm_src[pos] = src[e];
    }
}

// ---------------- K4b: edge-parallel exp (full-sector gather) --------------
// alpha[p][0..7] = exp(enode[perm_src[p]][0..7]); one 32B sector in, coalesced out
__global__ void k4b_exp(void)
{
    int p = blockIdx.x * blockDim.x + threadIdx.x;
    if (p >= N_EDGES) return;
    int s = g_perm_src[p];
    float4 a = *(const float4*)&g_enode[(size_t)s*HEADS];
    float4 b = *(const float4*)&g_enode[(size_t)s*HEADS + 4];
    float4 ea = make_float4(__expf(a.x), __expf(a.y), __expf(a.z), __expf(a.w));
    float4 eb = make_float4(__expf(b.x), __expf(b.y), __expf(b.z), __expf(b.w));
    *(float4*)&g_alpha[(size_t)p*HEADS]     = ea;
    *(float4*)&g_alpha[(size_t)p*HEADS + 4] = eb;
}

// ---------------- K5a: per-dst denom + normalize in place ------------------
// warp per dst; eexp reads/writes contiguous. stride 32 keeps lane's head fixed.
__global__ __launch_bounds__(256) void k5a_denom(void)
{
    int d = blockIdx.x * 8 + (threadIdx.x >> 5);
    int lane = threadIdx.x & 31;
    if (d >= N_ARGS) return;
    int beg = g_offsets[d];
    int n = (g_offsets[d+1] - beg) * HEADS;
    float* p = g_alpha + (size_t)beg * HEADS;
    float sv = 0.f;
    for (int i = lane; i < n; i += 32) sv += p[i];
    sv += __shfl_xor_sync(0xffffffffu, sv, 8);
    sv += __shfl_xor_sync(0xffffffffu, sv, 16);
    float r = 1.0f / sv;                 // n==0 -> inf, loop below empty
    for (int i = lane; i < n; i += 32) p[i] *= r;
}

// ---------------- K5: weighted gather only (alphas precomputed) ------------
// 384 threads; thread owns cols (2*tid, 2*tid+1); group-of-4 prefetch (MLP 4).
__global__ __launch_bounds__(384) void k5_aggregate(const float* __restrict__ h)
{
    __shared__ unsigned long long alpha2_s[64*HEADS];
    __shared__ int src_s[64];

    int d   = blockIdx.x;
    int tid = threadIdx.x;

    int beg = g_offsets[d];
    int cnt = g_offsets[d+1] - beg;

    unsigned long long acc2[8];
    #pragma unroll
    for (int hh = 0; hh < 8; hh++) acc2[hh] = 0ull;

    for (int c0 = 0; c0 < cnt; c0 += 64) {
        int rem = min(64, cnt - c0);
        if (tid < rem) src_s[tid] = g_perm_src[beg + c0 + tid];
        for (int t = tid; t < rem * 8; t += 384) {
            float al = g_alpha[(size_t)(beg + c0)*HEADS + t];
            unsigned int ab = __float_as_uint(al);
            alpha2_s[t] = ((unsigned long long)ab << 32) | (unsigned long long)ab;
        }
        __syncthreads();

        int i = 0;
        for (; i + 4 <= rem; i += 4) {
            unsigned long long x[4];
            #pragma unroll
            for (int q = 0; q < 4; q++)
                x[q] = ((const unsigned long long*)(h + (size_t)src_s[i+q]*IN_DIM))[tid];
            #pragma unroll
            for (int q = 0; q < 4; q++) {
                const unsigned long long* ap = &alpha2_s[(i+q)*8];
                #pragma unroll
                for (int hh = 0; hh < 8; hh++)
                    acc2[hh] = fma_f32x2(ap[hh], x[q], acc2[hh]);
            }
        }
        for (; i < rem; i++) {
            unsigned long long x =
                ((const unsigned long long*)(h + (size_t)src_s[i]*IN_DIM))[tid];
            const unsigned long long* ap = &alpha2_s[i*8];
            #pragma unroll
            for (int hh = 0; hh < 8; hh++)
                acc2[hh] = fma_f32x2(ap[hh], x, acc2[hh]);
        }
        __syncthreads();
    }

    // epilogue: fp16 plane [head][d][k]
    #pragma unroll
    for (int hh = 0; hh < 8; hh++) {
        float vlo = __uint_as_float((unsigned int)acc2[hh]);
        float vhi = __uint_as_float((unsigned int)(acc2[hh] >> 32));
        __half2 hv = __floats2half2_rn(vlo, vhi);
        size_t base = ((size_t)hh*N_ARGS + d)*IN_DIM + 2*tid;
        *(__half2*)&g_hbar[base] = hv;
    }
}

// ---------------- K6: fp16 MMA GEMM, A fp16, B fp16 hi/lo, cp.async 3-stage -
#define GBM 128
#define GBN 64
#define GBK2 32
#define KPAD2 40
#define STAGES 3
#define A_ELE (GBM*KPAD2)             // 5120
#define B_ELE (GBN*KPAD2)             // 2560
#define STAGE_ELE (A_ELE + 2*B_ELE)   // 10240 halves = 20480 B
#define K6_SMEM (STAGES*STAGE_ELE*2)  // 61440 B

__device__ __forceinline__ void ldsm4(uint32_t* r, const void* p)
{
    uint32_t a = (uint32_t)__cvta_generic_to_shared(p);
    asm volatile("ldmatrix.sync.aligned.m8n8.x4.shared.b16 {%0,%1,%2,%3}, [%4];"
        : "=r"(r[0]), "=r"(r[1]), "=r"(r[2]), "=r"(r[3]) : "r"(a));
}
__device__ __forceinline__ void mma16816f(float* c, const uint32_t* a, const uint32_t* b)
{
    asm volatile("mma.sync.aligned.m16n8k16.row.col.f32.f16.f16.f32 "
        "{%0,%1,%2,%3},{%4,%5,%6,%7},{%8,%9},{%0,%1,%2,%3};"
        : "+f"(c[0]), "+f"(c[1]), "+f"(c[2]), "+f"(c[3])
        : "r"(a[0]), "r"(a[1]), "r"(a[2]), "r"(a[3]), "r"(b[0]), "r"(b[1]));
}
__device__ __forceinline__ void cp16(void* smem_dst, const void* gsrc, int src_size)
{
    uint32_t s = (uint32_t)__cvta_generic_to_shared(smem_dst);
    asm volatile("cp.async.cg.shared.global [%0], [%1], 16, %2;"
        :: "r"(s), "l"(gsrc), "r"(src_size));
}

__global__ __launch_bounds__(256) void k6_mma(float* __restrict__ out)
{
    extern __shared__ __half sm[];

    int tid = threadIdx.x;
    int d0  = blockIdx.x * GBM;
    int hh  = blockIdx.y;

    const __half* A  = g_hbar + (size_t)hh*N_ARGS*IN_DIM;
    const __half* Bh = g_Whf + (size_t)hh*OUT_DIM*IN_DIM;
    const __half* Bl = g_Wlf + (size_t)hh*OUT_DIM*IN_DIM;

    int ar0 = tid >> 2,        as0 = (tid & 3) * 8;
    int ar1 = (tid+256) >> 2;
    int br  = tid >> 2;

    int add0 = d0 + ar0, add1 = d0 + ar1;
    int av0 = (add0 < N_ARGS) ? 16 : 0;
    int av1 = (add1 < N_ARGS) ? 16 : 0;
    if (add0 >= N_ARGS) add0 = N_ARGS-1;
    if (add1 >= N_ARGS) add1 = N_ARGS-1;

    auto issue_stage = [&](int slot, int kbase) {
        __half* st  = sm + slot*STAGE_ELE;
        __half* sA  = st;
        __half* sBh = st + A_ELE;
        __half* sBl = st + A_ELE + B_ELE;
        cp16(sA + ar0*KPAD2 + as0, A + (size_t)add0*IN_DIM + kbase + as0, av0);
        cp16(sA + ar1*KPAD2 + as0, A + (size_t)add1*IN_DIM + kbase + as0, av1);
        cp16(sBh + br*KPAD2 + as0, Bh + (size_t)br*IN_DIM + kbase + as0, 16);
        cp16(sBl + br*KPAD2 + as0, Bl + (size_t)br*IN_DIM + kbase + as0, 16);
        asm volatile("cp.async.commit_group;");
    };

    int w    = tid >> 5;
    int lane = tid & 31;
    int wm   = (w & 3) * 32;
    int wn   = (w >> 2) * 32;

    int a_row = (lane & 15);
    int a_kof = (lane >> 4) * 8;
    int b_row = ((lane >> 4) << 3) + (lane & 7);
    int b_kof = (lane & 8);

    float acc[2][4][4];
    #pragma unroll
    for (int i = 0; i < 2; i++)
        #pragma unroll
        for (int j = 0; j < 4; j++)
            #pragma unroll
            for (int q = 0; q < 4; q++) acc[i][j][q] = 0.f;

    issue_stage(0, 0);
    issue_stage(1, GBK2);

    const int KT = IN_DIM / GBK2;   // 24
    for (int kt = 0; kt < KT; kt++) {
        asm volatile("cp.async.wait_group 1;");
        __syncthreads();
        if (kt + 2 < KT) issue_stage((kt+2) % STAGES, (kt+2)*GBK2);

        int cur = kt % STAGES;
        __half* st  = sm + cur*STAGE_ELE;
        __half* sA  = st;
        __half* sBh = st + A_ELE;
        __half* sBl = st + A_ELE + B_ELE;

        #pragma unroll
        for (int kh = 0; kh < 2; kh++) {
            uint32_t a[2][4], bh[2][4], bl[2][4];
            #pragma unroll
            for (int mb = 0; mb < 2; mb++)
                ldsm4(a[mb], sA + (wm + mb*16 + a_row)*KPAD2 + a_kof + kh*16);
            #pragma unroll
            for (int nb = 0; nb < 2; nb++) {
                ldsm4(bh[nb], sBh + (wn + nb*16 + b_row)*KPAD2 + b_kof + kh*16);
                ldsm4(bl[nb], sBl + (wn + nb*16 + b_row)*KPAD2 + b_kof + kh*16);
            }
            #pragma unroll
            for (int mb = 0; mb < 2; mb++) {
                #pragma unroll
                for (int nb = 0; nb < 4; nb++) {
                    const uint32_t* bhf = &bh[nb>>1][(nb&1)*2];
                    const uint32_t* blf = &bl[nb>>1][(nb&1)*2];
                    mma16816f(acc[mb][nb], a[mb], bhf);
                    mma16816f(acc[mb][nb], a[mb], blf);
                }
            }
        }
        __syncthreads();
    }

    int erow = lane >> 2;
    int ecol = (lane & 3) * 2;
    #pragma unroll
    for (int mb = 0; mb < 2; mb++) {
        #pragma unroll
        for (int nb = 0; nb < 4; nb++) {
            int col = hh*OUT_DIM + wn + nb*8 + ecol;
            int r0 = d0 + wm + mb*16 + erow;
            int r1 = r0 + 8;
            if (r0 < N_ARGS)
                *(float2*)(out + (size_t)r0*Z_DIM + col) =
                    make_float2(acc[mb][nb][0], acc[mb][nb][1]);
            if (r1 < N_ARGS)
                *(float2*)(out + (size_t)r1*Z_DIM + col) =
                    make_float2(acc[mb][nb][2], acc[mb][nb][3]);
        }
    }
}

// ---------------- launch ----------------------------------------------------
extern "C" void kernel_launch(void* const* d_in, const int* in_sizes, int n_in,
                              void* d_out, int out_size)
{
    const float* h     = (const float*)d_in[0];
    const float* W_fc  = (const float*)d_in[1];
    const float* a_att = (const float*)d_in[2];
    const int*   esrc  = (const int*)d_in[3];
    const int*   edst  = (const int*)d_in[4];
    float* out = (float*)d_out;

    cudaFuncSetAttribute(k6_mma, cudaFuncAttributeMaxDynamicSharedMemorySize, K6_SMEM);

    k0_attn_proj<<<(HEADS*IN_DIM + 255)/256, 256>>>(W_fc, a_att);
    k0b_wsplit<<<(Z_DIM*IN_DIM + 255)/256, 256>>>(W_fc);
    k2b_hist<<<(N_EDGES + 255)/256, 256>>>(edst);
    k1_scores<<<(N_TOKENS/2 + 7)/8, 256>>>(h);     // slot 4 -> ncu profiles this
    k3_scan<<<1, 1024>>>();
    k4_scatter<<<(N_EDGES + 255)/256, 256>>>(esrc, edst);
    k4b_exp<<<(N_EDGES + 255)/256, 256>>>();
    k5a_denom<<<(N_ARGS + 7)/8, 256>>>();
    k5_aggregate<<<N_ARGS, 384>>>(h);
    dim3 g6((N_ARGS + GBM - 1)/GBM, HEADS);
    k6_mma<<<g6, 256, K6_SMEM>>>(out);
}